// round 6
// baseline (speedup 1.0000x reference)
#include <cuda_runtime.h>
#include <stdint.h>

#define RMS_EPS 1e-6f

// 256 threads/CTA, 16 elements/thread (H=4096). MLP_p1 = 8 front-batched
// 128-bit loads per thread to keep the L1tex queue full across the
// reduction barrier gap.
__global__ void __launch_bounds__(256)
dequant_add_rmsnorm_quant_kernel(const int*   __restrict__ x,
                                 const float* __restrict__ residual,
                                 const float* __restrict__ scale,
                                 const float* __restrict__ weight,
                                 const float* __restrict__ dqs,
                                 float*       __restrict__ out_q,   // output 0 (quantized values as f32)
                                 float*       __restrict__ res_out, // output 1 (res_new as f32)
                                 int H)
{
    const int row = blockIdx.x;
    const int tid = threadIdx.x;
    const size_t base = (size_t)row * (size_t)H;
    const int i0 = tid << 4;  // 16 elements per thread

    const float s = __ldg(scale + row) * __ldg(dqs);

    // ---- front-batched 128-bit loads (MLP_p1 = 8) ----
    int4 xv[4];
    float4 rv[4];
    #pragma unroll
    for (int j = 0; j < 4; j++)
        xv[j] = *(const int4*)(x + base + i0 + 4 * j);
    #pragma unroll
    for (int j = 0; j < 4; j++)
        rv[j] = *(const float4*)(residual + base + i0 + 4 * j);

    float r[16];
    #pragma unroll
    for (int j = 0; j < 4; j++) {
        r[4*j+0] = fmaf((float)xv[j].x, s, rv[j].x);
        r[4*j+1] = fmaf((float)xv[j].y, s, rv[j].y);
        r[4*j+2] = fmaf((float)xv[j].z, s, rv[j].z);
        r[4*j+3] = fmaf((float)xv[j].w, s, rv[j].w);
    }

    // res_new (output 1) while hot in registers
    #pragma unroll
    for (int j = 0; j < 4; j++)
        *(float4*)(res_out + base + i0 + 4 * j) =
            make_float4(r[4*j+0], r[4*j+1], r[4*j+2], r[4*j+3]);

    float ss = 0.f;
    #pragma unroll
    for (int i = 0; i < 16; i++) ss = fmaf(r[i], r[i], ss);

    // ---- block reduction: 8 warps ----
    #pragma unroll
    for (int o = 16; o > 0; o >>= 1)
        ss += __shfl_xor_sync(0xFFFFFFFFu, ss, o);

    __shared__ float wsum[8];
    __shared__ float inv_s;
    const int wid = tid >> 5, lid = tid & 31;
    if (lid == 0) wsum[wid] = ss;
    __syncthreads();
    if (tid < 32) {
        float v = (tid < 8) ? wsum[tid] : 0.f;
        #pragma unroll
        for (int o = 4; o > 0; o >>= 1)
            v += __shfl_xor_sync(0xFFFFFFFFu, v, o);
        if (tid == 0) inv_s = 1.0f / sqrtf(v / (float)H + RMS_EPS);
    }
    __syncthreads();
    const float inv = inv_s;

    // ---- normalize, weight, round-half-even, saturate ----
    #pragma unroll
    for (int j = 0; j < 4; j++) {
        const float4 wv = *(const float4*)(weight + i0 + 4 * j);
        float q0 = fminf(fmaxf(rintf(r[4*j+0] * inv * wv.x), -128.f), 127.f);
        float q1 = fminf(fmaxf(rintf(r[4*j+1] * inv * wv.y), -128.f), 127.f);
        float q2 = fminf(fmaxf(rintf(r[4*j+2] * inv * wv.z), -128.f), 127.f);
        float q3 = fminf(fmaxf(rintf(r[4*j+3] * inv * wv.w), -128.f), 127.f);
        *(float4*)(out_q + base + i0 + 4 * j) = make_float4(q0, q1, q2, q3);
    }
}

extern "C" void kernel_launch(void* const* d_in, const int* in_sizes, int n_in,
                              void* d_out, int out_size)
{
    const int*   x        = (const int*)  d_in[0];
    const float* residual = (const float*)d_in[1];
    const float* scale    = (const float*)d_in[2];
    const float* weight   = (const float*)d_in[3];
    const float* dqs      = (const float*)d_in[4];

    const int T  = in_sizes[2];   // scale is [T]
    const int H  = in_sizes[3];   // weight is [H]

    // Outputs cast to f32 and concatenated: [quant | res_new]
    float* out_q   = (float*)d_out;
    float* res_out = (float*)d_out + (size_t)out_size / 2;

    const int threads = H / 16;   // H=4096 -> 256
    dequant_add_rmsnorm_quant_kernel<<<T, threads>>>(
        x, residual, scale, weight, dqs, out_q, res_out, H);
}

// round 7
// speedup vs baseline: 1.1901x; 1.1901x over previous
#include <cuda_runtime.h>
#include <stdint.h>

#define RMS_EPS 1e-6f

// 1024 threads/CTA, 4 elements/thread (H=4096). 32 warps of independent
// load streams per CTA; MLP_p1 = 2 per thread.
__global__ void __launch_bounds__(1024)
dequant_add_rmsnorm_quant_kernel(const int*   __restrict__ x,
                                 const float* __restrict__ residual,
                                 const float* __restrict__ scale,
                                 const float* __restrict__ weight,
                                 const float* __restrict__ dqs,
                                 float*       __restrict__ out_q,   // output 0 (quantized values as f32)
                                 float*       __restrict__ res_out, // output 1 (res_new as f32)
                                 int H)
{
    const int row = blockIdx.x;
    const int tid = threadIdx.x;
    const size_t base = (size_t)row * (size_t)H;
    const int i0 = tid << 2;  // 4 elements per thread
    const int wid = tid >> 5, lid = tid & 31;

    const float s = __ldg(scale + row) * __ldg(dqs);

    // ---- front-batched 128-bit loads (MLP_p1 = 2) ----
    const int4   xa = *(const int4*)  (x        + base + i0);
    const float4 ra = *(const float4*)(residual + base + i0);

    float r[4];
    r[0] = fmaf((float)xa.x, s, ra.x);
    r[1] = fmaf((float)xa.y, s, ra.y);
    r[2] = fmaf((float)xa.z, s, ra.z);
    r[3] = fmaf((float)xa.w, s, ra.w);

    // res_new (output 1) while hot in registers
    *(float4*)(res_out + base + i0) = make_float4(r[0], r[1], r[2], r[3]);

    float ss = fmaf(r[0], r[0], fmaf(r[1], r[1], fmaf(r[2], r[2], r[3] * r[3])));

    // ---- block reduction: 32 warps ----
    #pragma unroll
    for (int o = 16; o > 0; o >>= 1)
        ss += __shfl_xor_sync(0xFFFFFFFFu, ss, o);

    __shared__ float wsum[32];
    __shared__ float inv_s;
    if (lid == 0) wsum[wid] = ss;
    __syncthreads();
    if (tid < 32) {
        float v = wsum[tid];
        #pragma unroll
        for (int o = 16; o > 0; o >>= 1)
            v += __shfl_xor_sync(0xFFFFFFFFu, v, o);
        if (tid == 0) inv_s = 1.0f / sqrtf(v / (float)H + RMS_EPS);
    }
    __syncthreads();
    const float inv = inv_s;

    // ---- normalize, weight, round-half-even, saturate ----
    const float4 wv = *(const float4*)(weight + i0);
    float q0 = fminf(fmaxf(rintf(r[0] * inv * wv.x), -128.f), 127.f);
    float q1 = fminf(fmaxf(rintf(r[1] * inv * wv.y), -128.f), 127.f);
    float q2 = fminf(fmaxf(rintf(r[2] * inv * wv.z), -128.f), 127.f);
    float q3 = fminf(fmaxf(rintf(r[3] * inv * wv.w), -128.f), 127.f);
    *(float4*)(out_q + base + i0) = make_float4(q0, q1, q2, q3);
}

extern "C" void kernel_launch(void* const* d_in, const int* in_sizes, int n_in,
                              void* d_out, int out_size)
{
    const int*   x        = (const int*)  d_in[0];
    const float* residual = (const float*)d_in[1];
    const float* scale    = (const float*)d_in[2];
    const float* weight   = (const float*)d_in[3];
    const float* dqs      = (const float*)d_in[4];

    const int T  = in_sizes[2];   // scale is [T]
    const int H  = in_sizes[3];   // weight is [H]

    // Outputs cast to f32 and concatenated: [quant | res_new]
    float* out_q   = (float*)d_out;
    float* res_out = (float*)d_out + (size_t)out_size / 2;

    const int threads = H / 4;   // H=4096 -> 1024
    dequant_add_rmsnorm_quant_kernel<<<T, threads>>>(
        x, residual, scale, weight, dqs, out_q, res_out, H);
}

// round 8
// speedup vs baseline: 1.2278x; 1.0317x over previous
#include <cuda_runtime.h>
#include <stdint.h>

#define RMS_EPS 1e-6f

// Optimal config from the warp-count sweep: 512 threads (16 warps),
// 8 elems/thread, MLP_p1 = 4 front-batched 128-bit loads, default
// cache policy on loads and stores. Single-barrier block reduction.
__global__ void __launch_bounds__(512)
dequant_add_rmsnorm_quant_kernel(const int*   __restrict__ x,
                                 const float* __restrict__ residual,
                                 const float* __restrict__ scale,
                                 const float* __restrict__ weight,
                                 const float* __restrict__ dqs,
                                 float*       __restrict__ out_q,   // output 0 (quantized values as f32)
                                 float*       __restrict__ res_out, // output 1 (res_new as f32)
                                 int H)
{
    const int row = blockIdx.x;
    const int tid = threadIdx.x;
    const size_t base = (size_t)row * (size_t)H;
    const int i0 = tid << 3;  // 8 elements per thread
    const int wid = tid >> 5, lid = tid & 31;

    const float s = __ldg(scale + row) * __ldg(dqs);

    // ---- front-batched 128-bit loads (MLP_p1 = 4) ----
    const int4   xa = *(const int4*)  (x        + base + i0);
    const int4   xb = *(const int4*)  (x        + base + i0 + 4);
    const float4 ra = *(const float4*)(residual + base + i0);
    const float4 rb = *(const float4*)(residual + base + i0 + 4);

    float r[8];
    r[0] = fmaf((float)xa.x, s, ra.x);
    r[1] = fmaf((float)xa.y, s, ra.y);
    r[2] = fmaf((float)xa.z, s, ra.z);
    r[3] = fmaf((float)xa.w, s, ra.w);
    r[4] = fmaf((float)xb.x, s, rb.x);
    r[5] = fmaf((float)xb.y, s, rb.y);
    r[6] = fmaf((float)xb.z, s, rb.z);
    r[7] = fmaf((float)xb.w, s, rb.w);

    // res_new (output 1) while hot in registers — default write-back store
    *(float4*)(res_out + base + i0)     = make_float4(r[0], r[1], r[2], r[3]);
    *(float4*)(res_out + base + i0 + 4) = make_float4(r[4], r[5], r[6], r[7]);

    float ss = 0.f;
    #pragma unroll
    for (int i = 0; i < 8; i++) ss = fmaf(r[i], r[i], ss);

    // ---- single-barrier block reduction: warp reduce -> smem ->
    //      one __syncthreads -> every warp redundantly reduces the
    //      16 partials via shuffles (no second barrier / broadcast) ----
    #pragma unroll
    for (int o = 16; o > 0; o >>= 1)
        ss += __shfl_xor_sync(0xFFFFFFFFu, ss, o);

    __shared__ float wsum[16];
    if (lid == 0) wsum[wid] = ss;
    __syncthreads();

    float v = wsum[lid & 15];   // lanes 0-15 / 16-31 read same addrs (broadcast, conflict-free)
    #pragma unroll
    for (int o = 8; o > 0; o >>= 1)
        v += __shfl_xor_sync(0xFFFFFFFFu, v, o);
    const float inv = 1.0f / sqrtf(v / (float)H + RMS_EPS);

    // ---- normalize, weight, round-half-even, saturate ----
    const float4 wa = *(const float4*)(weight + i0);
    const float4 wb = *(const float4*)(weight + i0 + 4);
    const float w[8] = {wa.x, wa.y, wa.z, wa.w, wb.x, wb.y, wb.z, wb.w};

    float q[8];
    #pragma unroll
    for (int i = 0; i < 8; i++) {
        float t = rintf(r[i] * inv * w[i]);      // jnp.round = half-to-even
        q[i] = fminf(fmaxf(t, -128.f), 127.f);   // clip; int8 value as f32
    }
    *(float4*)(out_q + base + i0)     = make_float4(q[0], q[1], q[2], q[3]);
    *(float4*)(out_q + base + i0 + 4) = make_float4(q[4], q[5], q[6], q[7]);
}

extern "C" void kernel_launch(void* const* d_in, const int* in_sizes, int n_in,
                              void* d_out, int out_size)
{
    const int*   x        = (const int*)  d_in[0];
    const float* residual = (const float*)d_in[1];
    const float* scale    = (const float*)d_in[2];
    const float* weight   = (const float*)d_in[3];
    const float* dqs      = (const float*)d_in[4];

    const int T  = in_sizes[2];   // scale is [T]
    const int H  = in_sizes[3];   // weight is [H]

    // Outputs cast to f32 and concatenated: [quant | res_new]
    float* out_q   = (float*)d_out;
    float* res_out = (float*)d_out + (size_t)out_size / 2;

    const int threads = H / 8;   // H=4096 -> 512
    dequant_add_rmsnorm_quant_kernel<<<T, threads>>>(
        x, residual, scale, weight, dqs, out_q, res_out, H);
}

// round 9
// speedup vs baseline: 1.2346x; 1.0055x over previous
#include <cuda_runtime.h>
#include <stdint.h>

#define RMS_EPS 1e-6f

// 256-bit global load/store helpers (sm_100+ / Blackwell).
__device__ __forceinline__ void ldg256(const float* p, float v[8]) {
    asm volatile("ld.global.v8.f32 {%0,%1,%2,%3,%4,%5,%6,%7}, [%8];"
        : "=f"(v[0]), "=f"(v[1]), "=f"(v[2]), "=f"(v[3]),
          "=f"(v[4]), "=f"(v[5]), "=f"(v[6]), "=f"(v[7])
        : "l"(p));
}
__device__ __forceinline__ void stg256(float* p, const float v[8]) {
    asm volatile("st.global.v8.f32 [%0], {%1,%2,%3,%4,%5,%6,%7,%8};"
        :: "l"(p),
           "f"(v[0]), "f"(v[1]), "f"(v[2]), "f"(v[3]),
           "f"(v[4]), "f"(v[5]), "f"(v[6]), "f"(v[7])
        : "memory");
}

// Champion config: 512 threads (16 warps), 8 elems/thread, now with
// 256-bit LDG/STG (2 loads + 2 stores per thread instead of 4+4).
__global__ void __launch_bounds__(512)
dequant_add_rmsnorm_quant_kernel(const int*   __restrict__ x,
                                 const float* __restrict__ residual,
                                 const float* __restrict__ scale,
                                 const float* __restrict__ weight,
                                 const float* __restrict__ dqs,
                                 float*       __restrict__ out_q,   // output 0 (quantized values as f32)
                                 float*       __restrict__ res_out, // output 1 (res_new as f32)
                                 int H)
{
    const int row = blockIdx.x;
    const int tid = threadIdx.x;
    const size_t base = (size_t)row * (size_t)H;
    const int i0 = tid << 3;  // 8 elements per thread (32B-aligned offsets)

    const float s = __ldg(scale + row) * __ldg(dqs);

    // ---- front-batched 256-bit loads (2 LDG.256 per thread) ----
    float xf[8], rf[8];
    ldg256((const float*)(x + base + i0), xf);   // int32 bits read as raw f32 regs
    ldg256(residual + base + i0, rf);

    float r[8];
    #pragma unroll
    for (int i = 0; i < 8; i++)
        r[i] = fmaf((float)__float_as_int(xf[i]), s, rf[i]);

    // res_new (output 1) while hot in registers — 256-bit store
    stg256(res_out + base + i0, r);

    float ss = 0.f;
    #pragma unroll
    for (int i = 0; i < 8; i++) ss = fmaf(r[i], r[i], ss);

    // ---- block reduction: 16 warps (proven structure) ----
    #pragma unroll
    for (int o = 16; o > 0; o >>= 1)
        ss += __shfl_xor_sync(0xFFFFFFFFu, ss, o);

    __shared__ float wsum[16];
    __shared__ float inv_s;
    const int wid = tid >> 5, lid = tid & 31;
    if (lid == 0) wsum[wid] = ss;
    __syncthreads();
    if (tid < 32) {
        float v = (tid < 16) ? wsum[tid] : 0.f;
        #pragma unroll
        for (int o = 8; o > 0; o >>= 1)
            v += __shfl_xor_sync(0xFFFFFFFFu, v, o);
        if (tid == 0) inv_s = 1.0f / sqrtf(v / (float)H + RMS_EPS);
    }
    __syncthreads();
    const float inv = inv_s;

    // ---- normalize, weight, round-half-even, saturate ----
    float w[8];
    ldg256(weight + i0, w);

    float q[8];
    #pragma unroll
    for (int i = 0; i < 8; i++) {
        float t = rintf(r[i] * inv * w[i]);      // jnp.round = half-to-even
        q[i] = fminf(fmaxf(t, -128.f), 127.f);   // clip; int8 value as f32
    }
    stg256(out_q + base + i0, q);
}

extern "C" void kernel_launch(void* const* d_in, const int* in_sizes, int n_in,
                              void* d_out, int out_size)
{
    const int*   x        = (const int*)  d_in[0];
    const float* residual = (const float*)d_in[1];
    const float* scale    = (const float*)d_in[2];
    const float* weight   = (const float*)d_in[3];
    const float* dqs      = (const float*)d_in[4];

    const int T  = in_sizes[2];   // scale is [T]
    const int H  = in_sizes[3];   // weight is [H]

    // Outputs cast to f32 and concatenated: [quant | res_new]
    float* out_q   = (float*)d_out;
    float* res_out = (float*)d_out + (size_t)out_size / 2;

    const int threads = H / 8;   // H=4096 -> 512
    dequant_add_rmsnorm_quant_kernel<<<T, threads>>>(
        x, residual, scale, weight, dqs, out_q, res_out, H);
}